// round 15
// baseline (speedup 1.0000x reference)
#include <cuda_runtime.h>
#include <cstdint>

typedef unsigned u32;
typedef unsigned short u16;

#define TT  2048
#define CH  128
#define NCH (TT/CH)
#define HID 512
#define NB  32
#define G4  (4*HID)
#define HK  (HID/2)   // 256 (k-pair index space)

#define XPROJ_VOL ((size_t)CH * G4 * NB)
#define XPACK_VOL ((size_t)CH * HK * NB)

// ---------------- device scratch (~91MB, double-buffered for overlap) ----------------
__device__ __align__(16) float g_xproj[2 * XPROJ_VOL];           // [buf][t_loc][g][b] fp32
__device__ __align__(16) u32   g_xhi[2 * XPACK_VOL];             // [buf][t][d2][b]
__device__ __align__(16) u32   g_xlo[2 * XPACK_VOL];
__device__ __align__(16) u32   g_wih_hi[G4 * HK];                // [g][d2]
__device__ __align__(16) u32   g_wih_lo[G4 * HK];
__device__ __align__(16) u32   g_whh_hi[G4 * HK];
__device__ __align__(16) u32   g_whh_lo[G4 * HK];
__device__ __align__(16) u32   g_hhi[2 * 4 * HK * 8];            // [par][grp][j2][b]
__device__ __align__(16) u32   g_hlo[2 * 4 * HK * 8];
__device__ __align__(16) float g_c[NB * HID];                    // cell state between chunks
__device__ u32 g_bar[128];                                       // [grp*32 + quarter*8]

// ---------------- helpers ----------------
__device__ __forceinline__ u32 bf16rn(u32 xb){ return (xb + 0x7FFFu + ((xb >> 16) & 1u)) >> 16; }
__device__ __forceinline__ void splitbf(float x, u32& hi, u32& lo){
    u32 xb = __float_as_uint(x);
    hi = bf16rn(xb);
    float r = x - __uint_as_float(hi << 16);
    lo = bf16rn(__float_as_uint(r));
}
__device__ __forceinline__ u32 packbf(float x){ u32 h, l; splitbf(x, h, l); return h | (l << 16); }
__device__ __forceinline__ u32 prmt(u32 a, u32 b, u32 s){
    u32 d; asm("prmt.b32 %0,%1,%2,%3;" : "=r"(d) : "r"(a), "r"(b), "r"(s)); return d;
}
__device__ __forceinline__ void mma_bf16(float* c, const u32* a, u32 b0, u32 b1){
    asm volatile("mma.sync.aligned.m16n8k16.row.col.f32.bf16.bf16.f32 "
                 "{%0,%1,%2,%3},{%4,%5,%6,%7},{%8,%9},{%0,%1,%2,%3};"
                 : "+f"(c[0]), "+f"(c[1]), "+f"(c[2]), "+f"(c[3])
                 : "r"(a[0]), "r"(a[1]), "r"(a[2]), "r"(a[3]), "r"(b0), "r"(b1));
}
__device__ __forceinline__ void cp16(u32* dst, const u32* src){
    u32 d = (u32)__cvta_generic_to_shared(dst);
    asm volatile("cp.async.cg.shared.global [%0], [%1], 16;" :: "r"(d), "l"(src));
}
__device__ __forceinline__ void cp_commit(){ asm volatile("cp.async.commit_group;" ::: "memory"); }
__device__ __forceinline__ void bar_arrive(u32* p){
    asm volatile("red.release.gpu.global.add.u32 [%0], %1;" :: "l"(p), "r"(1u) : "memory");
}
__device__ __forceinline__ u32 ld_acq(const u32* p){
    u32 v; asm volatile("ld.acquire.gpu.global.u32 %0, [%1];" : "=r"(v) : "l"(p) : "memory"); return v;
}
__device__ __forceinline__ void barn(int id){ asm volatile("bar.sync %0, 128;" :: "r"(id) : "memory"); }
__device__ __forceinline__ void barn64(int id){ asm volatile("bar.sync %0, 64;" :: "r"(id) : "memory"); }
__device__ __forceinline__ float sigm(float x){ return 1.f / (1.f + __expf(-x)); }

// ---------------- kernel 1: reset barriers ----------------
__global__ void k_init(){
    if (threadIdx.x < 128) g_bar[threadIdx.x] = 0;
}

// ---------------- kernel 2: pack weights into hi/lo planes ----------------
__global__ void k_packw(const float* __restrict__ wih, const float* __restrict__ whh){
    int id = blockIdx.x * 256 + threadIdx.x;            // 262144 float4s per matrix
    {
        float4 a = ((const float4*)wih)[id];
        u32 p0 = packbf(a.x), p1 = packbf(a.y), p2 = packbf(a.z), p3 = packbf(a.w);
        ((uint2*)g_wih_hi)[id] = make_uint2(prmt(p0, p1, 0x5410u), prmt(p2, p3, 0x5410u));
        ((uint2*)g_wih_lo)[id] = make_uint2(prmt(p0, p1, 0x7632u), prmt(p2, p3, 0x7632u));
    }
    {
        float4 a = ((const float4*)whh)[id];
        u32 p0 = packbf(a.x), p1 = packbf(a.y), p2 = packbf(a.z), p3 = packbf(a.w);
        ((uint2*)g_whh_hi)[id] = make_uint2(prmt(p0, p1, 0x5410u), prmt(p2, p3, 0x5410u));
        ((uint2*)g_whh_lo)[id] = make_uint2(prmt(p0, p1, 0x7632u), prmt(p2, p3, 0x7632u));
    }
}

// ---------------- kernel 3: transpose + pack input chunk into hi/lo planes ----------------
__global__ void k_packx(const float* __restrict__ input, int tbase, int buf){
    __shared__ u32 tile[32 * 129];
    int tl = blockIdx.y, d0 = blockIdx.x * 128, tid = threadIdx.x;
    int t = tbase + tl;
    #pragma unroll
    for (int i = 0; i < 4; i++){
        int id = tid + i * 256;                          // 1024 float4s: [b][q]
        int b = id >> 5, q = id & 31;
        float4 v = *(const float4*)(input + ((size_t)b * TT + t) * HID + d0 + q * 4);
        u32* tp = &tile[b * 129 + q * 4];
        tp[0] = packbf(v.x); tp[1] = packbf(v.y); tp[2] = packbf(v.z); tp[3] = packbf(v.w);
    }
    __syncthreads();
    #pragma unroll
    for (int i = 0; i < 8; i++){
        int id = tid + i * 256;                          // 2048: [r2][b]
        int r2 = id >> 5, b = id & 31;
        u32 p0 = tile[b * 129 + 2 * r2], p1 = tile[b * 129 + 2 * r2 + 1];
        size_t o = (size_t)buf * XPACK_VOL + ((size_t)tl * HK + (d0 >> 1) + r2) * NB + b;
        g_xhi[o] = prmt(p0, p1, 0x5410u);
        g_xlo[o] = prmt(p0, p1, 0x7632u);
    }
}

// ---------------- kernel 4: xproj GEMM chunk (bf16x3, pre-split planes) ----------------
#define SWH 20
#define SX  72
#define BUFU (2*128*SWH + 2*16*SX)   // 7424 u32 per buffer

__device__ __forceinline__ void stage1(u32* buf, int tid, int g0, int t0, int kc, size_t xoff){
    u32* Whi = buf;
    u32* Wlo = buf + 128 * SWH;
    u32* Xhi = buf + 2 * 128 * SWH;
    u32* Xlo = Xhi + 16 * SX;
    const int k2_0 = kc * 16;
    #pragma unroll
    for (int i = 0; i < 4; i++){
        int id = i * 256 + tid;                 // [0,1024)
        int plane = id >> 9, rem = id & 511;
        int row = rem >> 2, c = rem & 3;
        u32* dst = (plane ? Wlo : Whi) + row * SWH + c * 4;
        const u32* src = (plane ? g_wih_lo : g_wih_hi) + (size_t)(g0 + row) * HK + k2_0 + c * 4;
        cp16(dst, src);
    }
    #pragma unroll
    for (int i = 0; i < 2; i++){
        int id = i * 256 + tid;                 // [0,512)
        int plane = id >> 8, rem = id & 255;
        int k2 = rem >> 4, c = rem & 15;
        u32* dst = (plane ? Xlo : Xhi) + k2 * SX + c * 4;
        const u32* src = (plane ? g_xlo : g_xhi) + xoff
            + ((size_t)(t0 + (c >> 3)) * HK + k2_0 + k2) * NB + (c & 7) * 4;
        cp16(dst, src);
    }
    cp_commit();
}

__global__ void __launch_bounds__(256) k_gemm1(const float* __restrict__ bih,
                                               const float* __restrict__ bhh, int xbuf){
    extern __shared__ u32 sm[];
    __shared__ float bias[128];
    const int tid = threadIdx.x, lane = tid & 31, warp = tid >> 5;
    const int gid = lane >> 2, tig = lane & 3;
    const int m = warp;
    const int g0 = blockIdx.x * 128, t0 = blockIdx.y * 2;   // chunk-local t
    const size_t xoff = (size_t)xbuf * XPACK_VOL;
    if (tid < 128) bias[tid] = bih[g0 + tid] + bhh[g0 + tid];

    float acc[8][4];
    #pragma unroll
    for (int n = 0; n < 8; n++){ acc[n][0]=0.f; acc[n][1]=0.f; acc[n][2]=0.f; acc[n][3]=0.f; }

    stage1(sm, tid, g0, t0, 0, xoff);
    for (int kc = 0; kc < 16; kc++){
        if (kc < 15){
            stage1(sm + ((kc + 1) & 1) * BUFU, tid, g0, t0, kc + 1, xoff);
            asm volatile("cp.async.wait_group 1;" ::: "memory");
        } else {
            asm volatile("cp.async.wait_group 0;" ::: "memory");
        }
        __syncthreads();
        const u32* Whi = sm + (kc & 1) * BUFU;
        const u32* Wlo = Whi + 128 * SWH;
        const u32* Xhi = Whi + 2 * 128 * SWH;
        const u32* Xlo = Xhi + 16 * SX;
        #pragma unroll
        for (int kt = 0; kt < 2; kt++){
            const int kb2 = kt * 8;
            u32 ahi[4], alo[4];
            #pragma unroll
            for (int p = 0; p < 4; p++){
                int row  = m * 16 + gid + ((p & 1) ? 8 : 0);
                int col2 = kb2 + tig + ((p >= 2) ? 4 : 0);
                ahi[p] = Whi[row * SWH + col2];
                alo[p] = Wlo[row * SWH + col2];
            }
            #pragma unroll
            for (int nt = 0; nt < 8; nt++){
                int n0 = nt * 8 + gid;
                u32 bh0 = Xhi[(kb2 + tig    ) * SX + n0];
                u32 bh1 = Xhi[(kb2 + tig + 4) * SX + n0];
                u32 bl0 = Xlo[(kb2 + tig    ) * SX + n0];
                u32 bl1 = Xlo[(kb2 + tig + 4) * SX + n0];
                mma_bf16(acc[nt], ahi, bh0, bh1);
                mma_bf16(acc[nt], ahi, bl0, bl1);
                mma_bf16(acc[nt], alo, bh0, bh1);
            }
        }
        __syncthreads();
    }
    float bz = bias[m * 16 + gid], bo = bias[m * 16 + gid + 8];
    #pragma unroll
    for (int nt = 0; nt < 8; nt++){
        int n0 = nt * 8 + 2 * tig;
        int t = t0 + (n0 >> 5), b = n0 & 31;
        int gr = g0 + m * 16 + gid;
        size_t o = (size_t)xbuf * XPROJ_VOL + ((size_t)t * G4 + gr) * NB + b;
        *(float2*)(g_xproj + o)          = make_float2(acc[nt][0] + bz, acc[nt][1] + bz);
        *(float2*)(g_xproj + o + 8 * NB) = make_float2(acc[nt][2] + bo, acc[nt][3] + bo);
    }
}

// ---------------- kernel 5: persistent recurrence (quarter barriers, shfl epilogue) ----------------
// Warp pair w (warps 2w, 2w+1 = kh 0/1) owns units j0 + w*4 .. +3 across ALL 4 gates:
//   A-fragment row r (0..15): gate = r>>2, unit = j0 + w*4 + (r&3)
// After kh-reduction, kh0 thread (gid,tig) holds gates {gid>>2, (gid>>2)+2} for its unit at
// cols 2tig/2tig+1; shfl.xor 16 exchanges with gates {., .} partner -> full gate set in-register.
__global__ void __launch_bounds__(256, 1) k_rec(const float* __restrict__ h0,
                                                const float* __restrict__ c0,
                                                float* __restrict__ out, int s0, int xbuf){
    __shared__ u32   Hshi[HK * 8];     // [j2][b] hi plane (stride 8, conflict-free)
    __shared__ u32   Hslo[HK * 8];
    __shared__ float Red[2][512];      // [par][w*32+lane][4] kh1 partial sums

    const int tid = threadIdx.x, lane = tid & 31, warp = tid >> 5;
    const int gid = lane >> 2, tig = lane & 3;
    const int w = warp >> 1, kh = warp & 1;
    const int gidx = w * 32 + lane;                    // [0,128) within kh-half
    const int group = blockIdx.x >> 5, sub = blockIdx.x & 31;
    const int j0 = sub * 16, b0g = group * 8;
    const int myq = sub >> 3;                          // quarter this sub publishes to

    // preload W_hh A-fragments (gate-sliced row map)
    u32 ahi[16][4], alo[16][4];
    #pragma unroll
    for (int kt = 0; kt < 16; kt++){
        int kb2 = kh * 128 + kt * 8;
        #pragma unroll
        for (int p = 0; p < 4; p++){
            int r    = gid + ((p & 1) ? 8 : 0);
            int grow = (r >> 2) * HID + j0 + w * 4 + (r & 3);
            int col2 = kb2 + tig + ((p >= 2) ? 4 : 0);
            ahi[kt][p] = g_whh_hi[(size_t)grow * HK + col2];
            alo[kt][p] = g_whh_lo[(size_t)grow * HK + col2];
        }
    }

    // per-thread (unit, batch) ownership (kh0 only)
    const int u  = w * 4 + (gid & 3);
    const int bb = 2 * tig + ((gid >= 4) ? 1 : 0);
    const int j  = j0 + u;
    float creg = 0.f;

    const size_t hbase_grp = (size_t)group * (HK * 8);

    // prologue
    if (kh == 0){
        if (s0 == 0){
            float h = h0[(size_t)(b0g + bb) * HID + j];
            u32 hi, lo; splitbf(h, hi, lo);
            size_t idx = hbase_grp + (j >> 1) * 8 + bb;             // parity 0
            ((u16*)(g_hhi + idx))[j & 1] = (u16)hi;
            ((u16*)(g_hlo + idx))[j & 1] = (u16)lo;
            creg = c0[(size_t)(b0g + bb) * HID + j];
        } else {
            creg = g_c[(size_t)(b0g + bb) * HID + j];
        }
    }
    __syncthreads();
    if (tid == 0 && s0 == 0) bar_arrive(&g_bar[group * 32 + myq * 8]);

    // x addressing for this thread's 4 accum slots (kh0)
    size_t xoff0 = 0, xoff1 = 0;
    if (kh == 0){
        xoff0 = ((size_t)((gid >> 2) * HID + j)) * NB + b0g + 2 * tig;
        xoff1 = xoff0 + (size_t)2 * HID * NB;
    }
    const float* xbase = g_xproj + (size_t)xbuf * XPROJ_VOL;
    const int qA = kh * 2, qB = kh * 2 + 1;

    for (int sl = 0; sl < CH; sl++){
        const int s = s0 + sl;
        const u32 par = (u32)(s & 1);

        // prefetch xproj (independent of barriers)
        float2 xa = make_float2(0.f, 0.f), xb2 = make_float2(0.f, 0.f);
        if (kh == 0){
            const float* xp = xbase + (size_t)sl * (G4 * NB);
            xa  = *(const float2*)(xp + xoff0);
            xb2 = *(const float2*)(xp + xoff1);
        }

        const size_t hoff = (size_t)par * (4 * HK * 8) + hbase_grp;
        const u32 target = 8u * (u32)(s + 1);

        // poll + stage quarter A
        if (lane == 0){
            const u32* bp = &g_bar[group * 32 + qA * 8];
            long guard = 0;
            while (ld_acq(bp) < target && guard < (1L << 26)) guard++;
        }
        __syncwarp();
        cp16(Hshi + qA * 512 + gidx * 4, g_hhi + hoff + qA * 512 + gidx * 4);
        cp16(Hslo + qA * 512 + gidx * 4, g_hlo + hoff + qA * 512 + gidx * 4);
        cp_commit();

        // poll + stage quarter B
        if (lane == 0){
            const u32* bp = &g_bar[group * 32 + qB * 8];
            long guard = 0;
            while (ld_acq(bp) < target && guard < (1L << 26)) guard++;
        }
        __syncwarp();
        cp16(Hshi + qB * 512 + gidx * 4, g_hhi + hoff + qB * 512 + gidx * 4);
        cp16(Hslo + qB * 512 + gidx * 4, g_hlo + hoff + qB * 512 + gidx * 4);
        cp_commit();

        float aH[4] = {0.f,0.f,0.f,0.f}, aM[4] = {0.f,0.f,0.f,0.f}, aL[4] = {0.f,0.f,0.f,0.f};

        // MMA quarter A (its stage done), quarter B still in flight
        asm volatile("cp.async.wait_group 1;" ::: "memory");
        barn(1 + kh);
        #pragma unroll
        for (int kt = 0; kt < 8; kt++){
            int kb2 = kh * 128 + kt * 8;
            u32 bh0 = Hshi[(kb2 + tig    ) * 8 + gid];
            u32 bh1 = Hshi[(kb2 + tig + 4) * 8 + gid];
            u32 bl0 = Hslo[(kb2 + tig    ) * 8 + gid];
            u32 bl1 = Hslo[(kb2 + tig + 4) * 8 + gid];
            mma_bf16(aH, ahi[kt], bh0, bh1);
            mma_bf16(aM, ahi[kt], bl0, bl1);
            mma_bf16(aL, alo[kt], bh0, bh1);
        }
        // MMA quarter B
        asm volatile("cp.async.wait_group 0;" ::: "memory");
        barn(1 + kh);
        #pragma unroll
        for (int kt = 8; kt < 16; kt++){
            int kb2 = kh * 128 + kt * 8;
            u32 bh0 = Hshi[(kb2 + tig    ) * 8 + gid];
            u32 bh1 = Hshi[(kb2 + tig + 4) * 8 + gid];
            u32 bl0 = Hslo[(kb2 + tig    ) * 8 + gid];
            u32 bl1 = Hslo[(kb2 + tig + 4) * 8 + gid];
            mma_bf16(aH, ahi[kt], bh0, bh1);
            mma_bf16(aM, ahi[kt], bl0, bl1);
            mma_bf16(aL, alo[kt], bh0, bh1);
        }
        float a0 = aH[0] + aM[0] + aL[0];
        float a1 = aH[1] + aM[1] + aL[1];
        float a2 = aH[2] + aM[2] + aL[2];
        float a3 = aH[3] + aM[3] + aL[3];

        if (kh == 1){
            // hand partial sums to kh0 twin, then race ahead to next step
            float* rp = &Red[par][(w * 32 + lane) * 4];
            rp[0] = a0; rp[1] = a1; rp[2] = a2; rp[3] = a3;
            barn64(3 + w);
            barn(2);                       // kh1-half: Hs region reuse guard
        } else {
            barn64(3 + w);
            const float* rp = &Red[par][(w * 32 + lane) * 4];
            float pre0 = a0 + rp[0] + xa.x;
            float pre1 = a1 + rp[1] + xa.y;
            float pre2 = a2 + rp[2] + xb2.x;
            float pre3 = a3 + rp[3] + xb2.y;

            // exchange with gate-partner (lane ^ 16)
            float q0 = __shfl_xor_sync(0xffffffffu, pre0, 16);
            float q1 = __shfl_xor_sync(0xffffffffu, pre1, 16);
            float q2 = __shfl_xor_sync(0xffffffffu, pre2, 16);
            float q3 = __shfl_xor_sync(0xffffffffu, pre3, 16);

            float gi, gf, gg, go;
            if (gid < 4){ gi = sigm(pre0); gg = tanhf(pre2); gf = sigm(q0); go = sigm(q2); }
            else        { gf = sigm(pre1); go = sigm(pre3); gi = sigm(q1); gg = tanhf(q3); }

            float cn = gf * creg + gi * gg;
            creg = cn;
            float h = go * tanhf(cn);

            if (s == TT - 1){
                out[(size_t)(b0g + bb) * HID + j]                      = h;
                out[(size_t)NB * HID + (size_t)(b0g + bb) * HID + j]   = cn;
            } else {
                u32 hi, lo; splitbf(h, hi, lo);
                size_t idx = (size_t)((s + 1) & 1) * (4 * HK * 8) + hbase_grp + (j >> 1) * 8 + bb;
                ((u16*)(g_hhi + idx))[j & 1] = (u16)hi;
                ((u16*)(g_hlo + idx))[j & 1] = (u16)lo;
            }
            barn(1);                       // kh0-half: publishes visible + Hs reuse guard
            if (warp == 0 && lane == 0 && s < TT - 1)
                bar_arrive(&g_bar[group * 32 + myq * 8]);
        }
    }

    // persist cell state for next chunk
    if (s0 + CH < TT && kh == 0)
        g_c[(size_t)(b0g + bb) * HID + j] = creg;
}

// ---------------- launcher: fork-join dual-stream pipeline ----------------
extern "C" void kernel_launch(void* const* d_in, const int* in_sizes, int n_in,
                              void* d_out, int out_size){
    const float* input = (const float*)d_in[0];
    const float* h0    = (const float*)d_in[1];
    const float* c0    = (const float*)d_in[2];
    const float* W_ih  = (const float*)d_in[3];
    const float* W_hh  = (const float*)d_in[4];
    const float* b_ih  = (const float*)d_in[5];
    const float* b_hh  = (const float*)d_in[6];
    float* out = (float*)d_out;

    static cudaStream_t sA = nullptr, sB = nullptr;
    static cudaEvent_t evStart, evW, evG[NCH], evR[NCH], evEnd;
    static bool inited = false;
    if (!inited){
        cudaStreamCreateWithFlags(&sA, cudaStreamNonBlocking);
        cudaStreamCreateWithFlags(&sB, cudaStreamNonBlocking);
        cudaEventCreateWithFlags(&evStart, cudaEventDisableTiming);
        cudaEventCreateWithFlags(&evW,     cudaEventDisableTiming);
        cudaEventCreateWithFlags(&evEnd,   cudaEventDisableTiming);
        for (int c = 0; c < NCH; c++){
            cudaEventCreateWithFlags(&evG[c], cudaEventDisableTiming);
            cudaEventCreateWithFlags(&evR[c], cudaEventDisableTiming);
        }
        cudaFuncSetAttribute(k_gemm1, cudaFuncAttributeMaxDynamicSharedMemorySize, 2 * BUFU * 4);
        inited = true;
    }

    // fork from capture-origin (default) stream
    cudaEventRecord(evStart, 0);
    cudaStreamWaitEvent(sA, evStart, 0);
    cudaStreamWaitEvent(sB, evStart, 0);

    // stream A: init + weight pack (needed by both streams)
    k_init<<<1, 128, 0, sA>>>();
    k_packw<<<1024, 256, 0, sA>>>(W_ih, W_hh);
    cudaEventRecord(evW, sA);
    cudaStreamWaitEvent(sB, evW, 0);

    for (int c = 0; c < NCH; c++){
        // stream B: projection pipeline for chunk c (buffer c&1)
        if (c >= 2) cudaStreamWaitEvent(sB, evR[c - 2], 0);   // buffer reuse
        k_packx<<<dim3(4, CH), 256, 0, sB>>>(input, c * CH, c & 1);
        k_gemm1<<<dim3(16, CH / 2), 256, 2 * BUFU * 4, sB>>>(b_ih, b_hh, c & 1);
        cudaEventRecord(evG[c], sB);

        // stream A: recurrence for chunk c
        cudaStreamWaitEvent(sA, evG[c], 0);
        k_rec<<<128, 256, 0, sA>>>(h0, c0, out, c * CH, c & 1);
        cudaEventRecord(evR[c], sA);
    }

    // join back to origin stream
    cudaEventRecord(evEnd, sA);
    cudaStreamWaitEvent(0, evEnd, 0);
    cudaStreamWaitEvent(0, evG[NCH - 1], 0);
}

// round 16
// speedup vs baseline: 1.1533x; 1.1533x over previous
#include <cuda_runtime.h>
#include <cstdint>

typedef unsigned u32;
typedef unsigned short u16;

#define TT  2048
#define CH  128
#define NCH (TT/CH)
#define HID 512
#define NB  32
#define G4  (4*HID)
#define HK  (HID/2)   // 256 (k-pair index space)

#define XPROJ_VOL ((size_t)CH * G4 * NB)
#define XPACK_VOL ((size_t)CH * HK * NB)

// ---------------- device scratch (~91MB, double-buffered for overlap) ----------------
__device__ __align__(16) float g_xproj[2 * XPROJ_VOL];           // [buf][t_loc][g][b] fp32
__device__ __align__(16) u32   g_xhi[2 * XPACK_VOL];             // [buf][t][d2][b]
__device__ __align__(16) u32   g_xlo[2 * XPACK_VOL];
__device__ __align__(16) u32   g_wih_hi[G4 * HK];                // [g][d2]
__device__ __align__(16) u32   g_wih_lo[G4 * HK];
__device__ __align__(16) u32   g_whh_hi[G4 * HK];
__device__ __align__(16) u32   g_whh_lo[G4 * HK];
__device__ __align__(16) u32   g_hhi[2 * 4 * HK * 8];            // [par][grp][j2][b]
__device__ __align__(16) u32   g_hlo[2 * 4 * HK * 8];
__device__ __align__(16) float g_c[NB * HID];                    // cell state between chunks
__device__ u32 g_bar[128];                                       // [grp*32 + half*8]

// ---------------- helpers ----------------
__device__ __forceinline__ u32 bf16rn(u32 xb){ return (xb + 0x7FFFu + ((xb >> 16) & 1u)) >> 16; }
__device__ __forceinline__ void splitbf(float x, u32& hi, u32& lo){
    u32 xb = __float_as_uint(x);
    hi = bf16rn(xb);
    float r = x - __uint_as_float(hi << 16);
    lo = bf16rn(__float_as_uint(r));
}
__device__ __forceinline__ u32 packbf(float x){ u32 h, l; splitbf(x, h, l); return h | (l << 16); }
__device__ __forceinline__ u32 prmt(u32 a, u32 b, u32 s){
    u32 d; asm("prmt.b32 %0,%1,%2,%3;" : "=r"(d) : "r"(a), "r"(b), "r"(s)); return d;
}
__device__ __forceinline__ void mma_bf16(float* c, const u32* a, u32 b0, u32 b1){
    asm volatile("mma.sync.aligned.m16n8k16.row.col.f32.bf16.bf16.f32 "
                 "{%0,%1,%2,%3},{%4,%5,%6,%7},{%8,%9},{%0,%1,%2,%3};"
                 : "+f"(c[0]), "+f"(c[1]), "+f"(c[2]), "+f"(c[3])
                 : "r"(a[0]), "r"(a[1]), "r"(a[2]), "r"(a[3]), "r"(b0), "r"(b1));
}
__device__ __forceinline__ void cp16(u32* dst, const u32* src){
    u32 d = (u32)__cvta_generic_to_shared(dst);
    asm volatile("cp.async.cg.shared.global [%0], [%1], 16;" :: "r"(d), "l"(src));
}
__device__ __forceinline__ void cp_commit(){ asm volatile("cp.async.commit_group;" ::: "memory"); }
__device__ __forceinline__ void bar_arrive(u32* p){
    asm volatile("red.release.gpu.global.add.u32 [%0], %1;" :: "l"(p), "r"(1u) : "memory");
}
__device__ __forceinline__ u32 ld_acq(const u32* p){
    u32 v; asm volatile("ld.acquire.gpu.global.u32 %0, [%1];" : "=r"(v) : "l"(p) : "memory"); return v;
}
__device__ __forceinline__ void barn(int id){ asm volatile("bar.sync %0, 128;" :: "r"(id) : "memory"); }
__device__ __forceinline__ void barn64(int id){ asm volatile("bar.sync %0, 64;" :: "r"(id) : "memory"); }
__device__ __forceinline__ float sigm(float x){ return 1.f / (1.f + __expf(-x)); }

// ---------------- kernel 1: reset barriers ----------------
__global__ void k_init(){
    if (threadIdx.x < 128) g_bar[threadIdx.x] = 0;
}

// ---------------- kernel 2: pack weights into hi/lo planes ----------------
__global__ void k_packw(const float* __restrict__ wih, const float* __restrict__ whh){
    int id = blockIdx.x * 256 + threadIdx.x;            // 262144 float4s per matrix
    {
        float4 a = ((const float4*)wih)[id];
        u32 p0 = packbf(a.x), p1 = packbf(a.y), p2 = packbf(a.z), p3 = packbf(a.w);
        ((uint2*)g_wih_hi)[id] = make_uint2(prmt(p0, p1, 0x5410u), prmt(p2, p3, 0x5410u));
        ((uint2*)g_wih_lo)[id] = make_uint2(prmt(p0, p1, 0x7632u), prmt(p2, p3, 0x7632u));
    }
    {
        float4 a = ((const float4*)whh)[id];
        u32 p0 = packbf(a.x), p1 = packbf(a.y), p2 = packbf(a.z), p3 = packbf(a.w);
        ((uint2*)g_whh_hi)[id] = make_uint2(prmt(p0, p1, 0x5410u), prmt(p2, p3, 0x5410u));
        ((uint2*)g_whh_lo)[id] = make_uint2(prmt(p0, p1, 0x7632u), prmt(p2, p3, 0x7632u));
    }
}

// ---------------- kernel 3: transpose + pack input chunk into hi/lo planes ----------------
__global__ void k_packx(const float* __restrict__ input, int tbase, int buf){
    __shared__ u32 tile[32 * 129];
    int tl = blockIdx.y, d0 = blockIdx.x * 128, tid = threadIdx.x;
    int t = tbase + tl;
    #pragma unroll
    for (int i = 0; i < 4; i++){
        int id = tid + i * 256;                          // 1024 float4s: [b][q]
        int b = id >> 5, q = id & 31;
        float4 v = *(const float4*)(input + ((size_t)b * TT + t) * HID + d0 + q * 4);
        u32* tp = &tile[b * 129 + q * 4];
        tp[0] = packbf(v.x); tp[1] = packbf(v.y); tp[2] = packbf(v.z); tp[3] = packbf(v.w);
    }
    __syncthreads();
    #pragma unroll
    for (int i = 0; i < 8; i++){
        int id = tid + i * 256;                          // 2048: [r2][b]
        int r2 = id >> 5, b = id & 31;
        u32 p0 = tile[b * 129 + 2 * r2], p1 = tile[b * 129 + 2 * r2 + 1];
        size_t o = (size_t)buf * XPACK_VOL + ((size_t)tl * HK + (d0 >> 1) + r2) * NB + b;
        g_xhi[o] = prmt(p0, p1, 0x5410u);
        g_xlo[o] = prmt(p0, p1, 0x7632u);
    }
}

// ---------------- kernel 4: xproj GEMM chunk (bf16x3, pre-split planes) ----------------
#define SWH 20
#define SX  72
#define BUFU (2*128*SWH + 2*16*SX)   // 7424 u32 per buffer

__device__ __forceinline__ void stage1(u32* buf, int tid, int g0, int t0, int kc, size_t xoff){
    u32* Whi = buf;
    u32* Wlo = buf + 128 * SWH;
    u32* Xhi = buf + 2 * 128 * SWH;
    u32* Xlo = Xhi + 16 * SX;
    const int k2_0 = kc * 16;
    #pragma unroll
    for (int i = 0; i < 4; i++){
        int id = i * 256 + tid;                 // [0,1024)
        int plane = id >> 9, rem = id & 511;
        int row = rem >> 2, c = rem & 3;
        u32* dst = (plane ? Wlo : Whi) + row * SWH + c * 4;
        const u32* src = (plane ? g_wih_lo : g_wih_hi) + (size_t)(g0 + row) * HK + k2_0 + c * 4;
        cp16(dst, src);
    }
    #pragma unroll
    for (int i = 0; i < 2; i++){
        int id = i * 256 + tid;                 // [0,512)
        int plane = id >> 8, rem = id & 255;
        int k2 = rem >> 4, c = rem & 15;
        u32* dst = (plane ? Xlo : Xhi) + k2 * SX + c * 4;
        const u32* src = (plane ? g_xlo : g_xhi) + xoff
            + ((size_t)(t0 + (c >> 3)) * HK + k2_0 + k2) * NB + (c & 7) * 4;
        cp16(dst, src);
    }
    cp_commit();
}

__global__ void __launch_bounds__(256) k_gemm1(const float* __restrict__ bih,
                                               const float* __restrict__ bhh, int xbuf){
    extern __shared__ u32 sm[];
    __shared__ float bias[128];
    const int tid = threadIdx.x, lane = tid & 31, warp = tid >> 5;
    const int gid = lane >> 2, tig = lane & 3;
    const int m = warp;
    const int g0 = blockIdx.x * 128, t0 = blockIdx.y * 2;   // chunk-local t
    const size_t xoff = (size_t)xbuf * XPACK_VOL;
    if (tid < 128) bias[tid] = bih[g0 + tid] + bhh[g0 + tid];

    float acc[8][4];
    #pragma unroll
    for (int n = 0; n < 8; n++){ acc[n][0]=0.f; acc[n][1]=0.f; acc[n][2]=0.f; acc[n][3]=0.f; }

    stage1(sm, tid, g0, t0, 0, xoff);
    for (int kc = 0; kc < 16; kc++){
        if (kc < 15){
            stage1(sm + ((kc + 1) & 1) * BUFU, tid, g0, t0, kc + 1, xoff);
            asm volatile("cp.async.wait_group 1;" ::: "memory");
        } else {
            asm volatile("cp.async.wait_group 0;" ::: "memory");
        }
        __syncthreads();
        const u32* Whi = sm + (kc & 1) * BUFU;
        const u32* Wlo = Whi + 128 * SWH;
        const u32* Xhi = Whi + 2 * 128 * SWH;
        const u32* Xlo = Xhi + 16 * SX;
        #pragma unroll
        for (int kt = 0; kt < 2; kt++){
            const int kb2 = kt * 8;
            u32 ahi[4], alo[4];
            #pragma unroll
            for (int p = 0; p < 4; p++){
                int row  = m * 16 + gid + ((p & 1) ? 8 : 0);
                int col2 = kb2 + tig + ((p >= 2) ? 4 : 0);
                ahi[p] = Whi[row * SWH + col2];
                alo[p] = Wlo[row * SWH + col2];
            }
            #pragma unroll
            for (int nt = 0; nt < 8; nt++){
                int n0 = nt * 8 + gid;
                u32 bh0 = Xhi[(kb2 + tig    ) * SX + n0];
                u32 bh1 = Xhi[(kb2 + tig + 4) * SX + n0];
                u32 bl0 = Xlo[(kb2 + tig    ) * SX + n0];
                u32 bl1 = Xlo[(kb2 + tig + 4) * SX + n0];
                mma_bf16(acc[nt], ahi, bh0, bh1);
                mma_bf16(acc[nt], ahi, bl0, bl1);
                mma_bf16(acc[nt], alo, bh0, bh1);
            }
        }
        __syncthreads();
    }
    float bz = bias[m * 16 + gid], bo = bias[m * 16 + gid + 8];
    #pragma unroll
    for (int nt = 0; nt < 8; nt++){
        int n0 = nt * 8 + 2 * tig;
        int t = t0 + (n0 >> 5), b = n0 & 31;
        int gr = g0 + m * 16 + gid;
        size_t o = (size_t)xbuf * XPROJ_VOL + ((size_t)t * G4 + gr) * NB + b;
        *(float2*)(g_xproj + o)          = make_float2(acc[nt][0] + bz, acc[nt][1] + bz);
        *(float2*)(g_xproj + o + 8 * NB) = make_float2(acc[nt][2] + bo, acc[nt][3] + bo);
    }
}

// ---------------- kernel 5: persistent recurrence ----------------
// R10 dataflow (single half-poll, single stage) + R15 register epilogue.
// Warp pair w (warps 2w,2w+1 = kh 0/1) owns units j0 + w*4..+3 across all 4 gates:
//   A-fragment row r (0..15): gate = r>>2, unit = j0 + w*4 + (r&3)
// After kh-pair reduction, shfl.xor 16 exchanges gate partners -> full gate set in-register.
__global__ void __launch_bounds__(256, 1) k_rec(const float* __restrict__ h0,
                                                const float* __restrict__ c0,
                                                float* __restrict__ out, int s0, int xbuf){
    __shared__ u32   Hshi[HK * 8];     // [j2][b] hi plane (stride 8, conflict-free)
    __shared__ u32   Hslo[HK * 8];
    __shared__ float Red[2][512];      // [par][w*32+lane][4] kh1 partial sums

    const int tid = threadIdx.x, lane = tid & 31, warp = tid >> 5;
    const int gid = lane >> 2, tig = lane & 3;
    const int w = warp >> 1, kh = warp & 1;
    const int gidx = w * 32 + lane;                    // [0,128) within kh-half
    const int group = blockIdx.x >> 5, sub = blockIdx.x & 31;
    const int j0 = sub * 16, b0g = group * 8;

    // preload W_hh A-fragments (gate-sliced row map)
    u32 ahi[16][4], alo[16][4];
    #pragma unroll
    for (int kt = 0; kt < 16; kt++){
        int kb2 = kh * 128 + kt * 8;
        #pragma unroll
        for (int p = 0; p < 4; p++){
            int r    = gid + ((p & 1) ? 8 : 0);
            int grow = (r >> 2) * HID + j0 + w * 4 + (r & 3);
            int col2 = kb2 + tig + ((p >= 2) ? 4 : 0);
            ahi[kt][p] = g_whh_hi[(size_t)grow * HK + col2];
            alo[kt][p] = g_whh_lo[(size_t)grow * HK + col2];
        }
    }

    // per-thread (unit, batch) ownership (kh0 only)
    const int u  = w * 4 + (gid & 3);
    const int bb = 2 * tig + ((gid >= 4) ? 1 : 0);
    const int j  = j0 + u;
    float creg = 0.f;

    const size_t hbase_grp = (size_t)group * (HK * 8);

    // prologue
    if (kh == 0){
        if (s0 == 0){
            float h = h0[(size_t)(b0g + bb) * HID + j];
            u32 hi, lo; splitbf(h, hi, lo);
            size_t idx = hbase_grp + (j >> 1) * 8 + bb;             // parity 0
            ((u16*)(g_hhi + idx))[j & 1] = (u16)hi;
            ((u16*)(g_hlo + idx))[j & 1] = (u16)lo;
            creg = c0[(size_t)(b0g + bb) * HID + j];
        } else {
            creg = g_c[(size_t)(b0g + bb) * HID + j];
        }
    }
    __syncthreads();
    if (tid == 0 && s0 == 0) bar_arrive(&g_bar[group * 32 + ((sub < 16) ? 0 : 8)]);

    // x addressing for this thread's 4 accum slots (kh0)
    size_t xoff0 = 0, xoff1 = 0;
    if (kh == 0){
        xoff0 = ((size_t)((gid >> 2) * HID + j)) * NB + b0g + 2 * tig;
        xoff1 = xoff0 + (size_t)2 * HID * NB;
    }
    const float* xbase = g_xproj + (size_t)xbuf * XPROJ_VOL;

    for (int sl = 0; sl < CH; sl++){
        const int s = s0 + sl;
        const u32 par = (u32)(s & 1);

        // prefetch xproj (independent of barrier)
        float2 xa = make_float2(0.f, 0.f), xb2 = make_float2(0.f, 0.f);
        if (kh == 0){
            const float* xp = xbase + (size_t)sl * (G4 * NB);
            xa  = *(const float2*)(xp + xoff0);
            xb2 = *(const float2*)(xp + xoff1);
        }

        // single per-half poll
        if (lane == 0){
            const u32* bp = &g_bar[group * 32 + kh * 8];
            u32 target = 16u * (u32)(s + 1);
            long guard = 0;
            while (ld_acq(bp) < target && guard < (1L << 26)) guard++;
        }
        __syncwarp();

        // stage this kh-half of h (both planes) into SMEM, one commit group
        {
            const size_t hoff = (size_t)par * (4 * HK * 8) + hbase_grp + (size_t)kh * 1024;
            #pragma unroll
            for (int i = 0; i < 2; i++){
                int id = gidx + i * 128;       // [0,256)
                cp16(Hshi + kh * 1024 + id * 4, g_hhi + hoff + id * 4);
                cp16(Hslo + kh * 1024 + id * 4, g_hlo + hoff + id * 4);
            }
            cp_commit();
        }
        asm volatile("cp.async.wait_group 0;" ::: "memory");
        barn(1 + kh);                          // all 4 warps of this half staged

        // MMA over this warp's K half — 3 independent accumulator chains
        float aH[4] = {0.f,0.f,0.f,0.f}, aM[4] = {0.f,0.f,0.f,0.f}, aL[4] = {0.f,0.f,0.f,0.f};
        #pragma unroll
        for (int kt = 0; kt < 16; kt++){
            int kb2 = kh * 128 + kt * 8;
            u32 bh0 = Hshi[(kb2 + tig    ) * 8 + gid];
            u32 bh1 = Hshi[(kb2 + tig + 4) * 8 + gid];
            u32 bl0 = Hslo[(kb2 + tig    ) * 8 + gid];
            u32 bl1 = Hslo[(kb2 + tig + 4) * 8 + gid];
            mma_bf16(aH, ahi[kt], bh0, bh1);
            mma_bf16(aM, ahi[kt], bl0, bl1);
            mma_bf16(aL, alo[kt], bh0, bh1);
        }
        float a0 = aH[0] + aM[0] + aL[0];
        float a1 = aH[1] + aM[1] + aL[1];
        float a2 = aH[2] + aM[2] + aL[2];
        float a3 = aH[3] + aM[3] + aL[3];

        if (kh == 1){
            // hand partial sums to kh0 twin
            float* rp = &Red[par][(w * 32 + lane) * 4];
            rp[0] = a0; rp[1] = a1; rp[2] = a2; rp[3] = a3;
            barn64(3 + w);
            barn(2);                       // kh1-half: Hs reuse guard before next stage
        } else {
            barn64(3 + w);
            const float* rp = &Red[par][(w * 32 + lane) * 4];
            float pre0 = a0 + rp[0] + xa.x;
            float pre1 = a1 + rp[1] + xa.y;
            float pre2 = a2 + rp[2] + xb2.x;
            float pre3 = a3 + rp[3] + xb2.y;

            // exchange with gate-partner (lane ^ 16)
            float q0 = __shfl_xor_sync(0xffffffffu, pre0, 16);
            float q1 = __shfl_xor_sync(0xffffffffu, pre1, 16);
            float q2 = __shfl_xor_sync(0xffffffffu, pre2, 16);
            float q3 = __shfl_xor_sync(0xffffffffu, pre3, 16);

            float gi, gf, gg, go;
            if (gid < 4){ gi = sigm(pre0); gg = tanhf(pre2); gf = sigm(q0); go = sigm(q2); }
            else        { gf = sigm(pre1); go = sigm(pre3); gi = sigm(q1); gg = tanhf(q3); }

            float cn = gf * creg + gi * gg;
            creg = cn;
            float h = go * tanhf(cn);

            if (s == TT - 1){
                out[(size_t)(b0g + bb) * HID + j]                      = h;
                out[(size_t)NB * HID + (size_t)(b0g + bb) * HID + j]   = cn;
            } else {
                u32 hi, lo; splitbf(h, hi, lo);
                size_t idx = (size_t)((s + 1) & 1) * (4 * HK * 8) + hbase_grp + (j >> 1) * 8 + bb;
                ((u16*)(g_hhi + idx))[j & 1] = (u16)hi;
                ((u16*)(g_hlo + idx))[j & 1] = (u16)lo;
            }
            barn(1);                       // kh0-half: publishes visible + Hs reuse guard
            if (warp == 0 && lane == 0 && s < TT - 1)
                bar_arrive(&g_bar[group * 32 + ((sub < 16) ? 0 : 8)]);
        }
    }

    // persist cell state for next chunk
    if (s0 + CH < TT && kh == 0)
        g_c[(size_t)(b0g + bb) * HID + j] = creg;
}

// ---------------- launcher: fork-join dual-stream pipeline ----------------
extern "C" void kernel_launch(void* const* d_in, const int* in_sizes, int n_in,
                              void* d_out, int out_size){
    const float* input = (const float*)d_in[0];
    const float* h0    = (const float*)d_in[1];
    const float* c0    = (const float*)d_in[2];
    const float* W_ih  = (const float*)d_in[3];
    const float* W_hh  = (const float*)d_in[4];
    const float* b_ih  = (const float*)d_in[5];
    const float* b_hh  = (const float*)d_in[6];
    float* out = (float*)d_out;

    static cudaStream_t sA = nullptr, sB = nullptr;
    static cudaEvent_t evStart, evW, evG[NCH], evR[NCH], evEnd;
    static bool inited = false;
    if (!inited){
        cudaStreamCreateWithFlags(&sA, cudaStreamNonBlocking);
        cudaStreamCreateWithFlags(&sB, cudaStreamNonBlocking);
        cudaEventCreateWithFlags(&evStart, cudaEventDisableTiming);
        cudaEventCreateWithFlags(&evW,     cudaEventDisableTiming);
        cudaEventCreateWithFlags(&evEnd,   cudaEventDisableTiming);
        for (int c = 0; c < NCH; c++){
            cudaEventCreateWithFlags(&evG[c], cudaEventDisableTiming);
            cudaEventCreateWithFlags(&evR[c], cudaEventDisableTiming);
        }
        cudaFuncSetAttribute(k_gemm1, cudaFuncAttributeMaxDynamicSharedMemorySize, 2 * BUFU * 4);
        inited = true;
    }

    // fork from capture-origin (default) stream
    cudaEventRecord(evStart, 0);
    cudaStreamWaitEvent(sA, evStart, 0);
    cudaStreamWaitEvent(sB, evStart, 0);

    // stream A: init + weight pack (needed by both streams)
    k_init<<<1, 128, 0, sA>>>();
    k_packw<<<1024, 256, 0, sA>>>(W_ih, W_hh);
    cudaEventRecord(evW, sA);
    cudaStreamWaitEvent(sB, evW, 0);

    for (int c = 0; c < NCH; c++){
        // stream B: projection pipeline for chunk c (buffer c&1)
        if (c >= 2) cudaStreamWaitEvent(sB, evR[c - 2], 0);   // buffer reuse
        k_packx<<<dim3(4, CH), 256, 0, sB>>>(input, c * CH, c & 1);
        k_gemm1<<<dim3(16, CH / 2), 256, 2 * BUFU * 4, sB>>>(b_ih, b_hh, c & 1);
        cudaEventRecord(evG[c], sB);

        // stream A: recurrence for chunk c
        cudaStreamWaitEvent(sA, evG[c], 0);
        k_rec<<<128, 256, 0, sA>>>(h0, c0, out, c * CH, c & 1);
        cudaEventRecord(evR[c], sA);
    }

    // join back to origin stream
    cudaEventRecord(evEnd, sA);
    cudaStreamWaitEvent(0, evEnd, 0);
    cudaStreamWaitEvent(0, evG[NCH - 1], 0);
}